// round 1
// baseline (speedup 1.0000x reference)
#include <cuda_runtime.h>
#include <math.h>

#define T_TOK 32768
#define C_DIM 768
#define E_NUM 4
#define HD_DIM 192

#define BM 64
#define BN 64
#define BK 32
#define PAD 4

// Scratch (allocation-free rule: __device__ globals)
__device__ float g_combine[T_TOK * E_NUM];                       // 512 KB
__device__ float g_hmid[(size_t)T_TOK * (E_NUM * HD_DIM)];       // 96 MB

// ---------------------------------------------------------------------------
// Router: one warp per token. 4 dots over C=768, softmax, top-2, renormalize.
// ---------------------------------------------------------------------------
__global__ __launch_bounds__(256) void router_kernel(
    const float* __restrict__ x,
    const float* __restrict__ rw,
    const float* __restrict__ rb)
{
    int warp = threadIdx.x >> 5;
    int lane = threadIdx.x & 31;
    int t = blockIdx.x * 8 + warp;
    const float* xr = x + (size_t)t * C_DIM;

    float a0 = 0.f, a1 = 0.f, a2 = 0.f, a3 = 0.f;
    for (int c = lane * 4; c < C_DIM; c += 32 * 4) {
        float4 xv = *(const float4*)(xr + c);
        float4 w0 = *(const float4*)(rw + 0 * C_DIM + c);
        float4 w1 = *(const float4*)(rw + 1 * C_DIM + c);
        float4 w2 = *(const float4*)(rw + 2 * C_DIM + c);
        float4 w3 = *(const float4*)(rw + 3 * C_DIM + c);
        a0 += xv.x * w0.x + xv.y * w0.y + xv.z * w0.z + xv.w * w0.w;
        a1 += xv.x * w1.x + xv.y * w1.y + xv.z * w1.z + xv.w * w1.w;
        a2 += xv.x * w2.x + xv.y * w2.y + xv.z * w2.z + xv.w * w2.w;
        a3 += xv.x * w3.x + xv.y * w3.y + xv.z * w3.z + xv.w * w3.w;
    }
    #pragma unroll
    for (int o = 16; o > 0; o >>= 1) {
        a0 += __shfl_xor_sync(0xffffffffu, a0, o);
        a1 += __shfl_xor_sync(0xffffffffu, a1, o);
        a2 += __shfl_xor_sync(0xffffffffu, a2, o);
        a3 += __shfl_xor_sync(0xffffffffu, a3, o);
    }
    if (lane == 0) {
        float l[4] = { a0 + rb[0], a1 + rb[1], a2 + rb[2], a3 + rb[3] };
        float mx = fmaxf(fmaxf(l[0], l[1]), fmaxf(l[2], l[3]));
        float p[4]; float Z = 0.f;
        #pragma unroll
        for (int e = 0; e < 4; e++) { p[e] = expf(l[e] - mx); Z += p[e]; }
        #pragma unroll
        for (int e = 0; e < 4; e++) p[e] /= Z;
        // top-2 (first occurrence wins on ties, matching lax.top_k)
        int i0 = 0;
        #pragma unroll
        for (int e = 1; e < 4; e++) if (p[e] > p[i0]) i0 = e;
        int i1 = (i0 == 0) ? 1 : 0;
        #pragma unroll
        for (int e = 0; e < 4; e++) if (e != i0 && p[e] > p[i1]) i1 = e;
        float s = p[i0] + p[i1] + 1e-8f;
        float outv[4] = { 0.f, 0.f, 0.f, 0.f };
        outv[i0] = p[i0] / s;
        outv[i1] = p[i1] / s;
        ((float4*)g_combine)[t] = make_float4(outv[0], outv[1], outv[2], outv[3]);
    }
}

// ---------------------------------------------------------------------------
// fc1 (per-expert GEMM-TN): hmid = gelu(x @ fc1_w[e]^T + fc1_b[e]) * combine
//   A = x [T, C], row-major (K-contiguous)
//   B = fc1_w[e] [HD, C], row-major (K-contiguous)
//   out -> g_hmid [T, E*HD]
// ---------------------------------------------------------------------------
__global__ __launch_bounds__(256) void fc1_kernel(
    const float* __restrict__ x,
    const float* __restrict__ w1,
    const float* __restrict__ b1)
{
    __shared__ float As[BK][BM + PAD];
    __shared__ float Bs[BK][BN + PAD];

    const int e  = blockIdx.z;
    const int m0 = blockIdx.y * BM;
    const int n0 = blockIdx.x * BN;
    const float* A = x  + (size_t)m0 * C_DIM;
    const float* B = w1 + (size_t)e * HD_DIM * C_DIM + (size_t)n0 * C_DIM;

    const int tid  = threadIdx.x;
    const int lrow = tid >> 3;          // 0..31
    const int lk   = (tid & 7) * 4;     // 0,4,...,28
    const int tx   = tid & 15;          // n sub-tile
    const int ty   = tid >> 4;          // m sub-tile

    float acc[4][4] = {};

    for (int k0 = 0; k0 < C_DIM; k0 += BK) {
        #pragma unroll
        for (int r = 0; r < 2; r++) {
            int row = lrow + r * 32;
            float4 v = *(const float4*)(A + (size_t)row * C_DIM + k0 + lk);
            As[lk + 0][row] = v.x; As[lk + 1][row] = v.y;
            As[lk + 2][row] = v.z; As[lk + 3][row] = v.w;
        }
        #pragma unroll
        for (int r = 0; r < 2; r++) {
            int row = lrow + r * 32;
            float4 v = *(const float4*)(B + (size_t)row * C_DIM + k0 + lk);
            Bs[lk + 0][row] = v.x; Bs[lk + 1][row] = v.y;
            Bs[lk + 2][row] = v.z; Bs[lk + 3][row] = v.w;
        }
        __syncthreads();
        #pragma unroll
        for (int k = 0; k < BK; k++) {
            float a[4], b[4];
            #pragma unroll
            for (int i = 0; i < 4; i++) a[i] = As[k][ty * 4 + i];
            #pragma unroll
            for (int j = 0; j < 4; j++) b[j] = Bs[k][tx * 4 + j];
            #pragma unroll
            for (int i = 0; i < 4; i++)
                #pragma unroll
                for (int j = 0; j < 4; j++)
                    acc[i][j] = fmaf(a[i], b[j], acc[i][j]);
        }
        __syncthreads();
    }

    #pragma unroll
    for (int i = 0; i < 4; i++) {
        int t = m0 + ty * 4 + i;
        float cw = g_combine[t * 4 + e];
        #pragma unroll
        for (int j = 0; j < 4; j++) {
            int h = n0 + tx * 4 + j;
            float v = acc[i][j] + b1[e * HD_DIM + h];
            float g = 0.5f * v * (1.f + erff(v * 0.70710678118654752f));
            g_hmid[(size_t)t * (E_NUM * HD_DIM) + e * HD_DIM + h] = g * cw;
        }
    }
}

// ---------------------------------------------------------------------------
// fc2: out[t,c] = sum_{e,h} hmid_w[t,e*HD+h] * fc2_w[e,c,h] + sum_e cw[e]*fc2_b[e,c]
//   A = g_hmid [T, 768] (K = E*HD = 768, K-contiguous)
//   B = fc2_w, per-k-tile expert index e = k0/HD (BK=32 divides HD=192)
// ---------------------------------------------------------------------------
__global__ __launch_bounds__(256) void fc2_kernel(
    const float* __restrict__ w2,
    const float* __restrict__ b2,
    float* __restrict__ out)
{
    __shared__ float As[BK][BM + PAD];
    __shared__ float Bs[BK][BN + PAD];

    const int m0 = blockIdx.y * BM;
    const int n0 = blockIdx.x * BN;

    const int tid  = threadIdx.x;
    const int lrow = tid >> 3;
    const int lk   = (tid & 7) * 4;
    const int tx   = tid & 15;
    const int ty   = tid >> 4;

    float acc[4][4] = {};

    for (int k0 = 0; k0 < E_NUM * HD_DIM; k0 += BK) {
        int e  = k0 / HD_DIM;
        int h0 = k0 - e * HD_DIM;
        const float* Bb = w2 + (size_t)e * C_DIM * HD_DIM + (size_t)n0 * HD_DIM + h0;
        #pragma unroll
        for (int r = 0; r < 2; r++) {
            int row = lrow + r * 32;
            float4 v = *(const float4*)(g_hmid + (size_t)(m0 + row) * (E_NUM * HD_DIM) + k0 + lk);
            As[lk + 0][row] = v.x; As[lk + 1][row] = v.y;
            As[lk + 2][row] = v.z; As[lk + 3][row] = v.w;
        }
        #pragma unroll
        for (int r = 0; r < 2; r++) {
            int row = lrow + r * 32;
            float4 v = *(const float4*)(Bb + (size_t)row * HD_DIM + lk);
            Bs[lk + 0][row] = v.x; Bs[lk + 1][row] = v.y;
            Bs[lk + 2][row] = v.z; Bs[lk + 3][row] = v.w;
        }
        __syncthreads();
        #pragma unroll
        for (int k = 0; k < BK; k++) {
            float a[4], b[4];
            #pragma unroll
            for (int i = 0; i < 4; i++) a[i] = As[k][ty * 4 + i];
            #pragma unroll
            for (int j = 0; j < 4; j++) b[j] = Bs[k][tx * 4 + j];
            #pragma unroll
            for (int i = 0; i < 4; i++)
                #pragma unroll
                for (int j = 0; j < 4; j++)
                    acc[i][j] = fmaf(a[i], b[j], acc[i][j]);
        }
        __syncthreads();
    }

    #pragma unroll
    for (int i = 0; i < 4; i++) {
        int t = m0 + ty * 4 + i;
        float4 cw = ((const float4*)g_combine)[t];
        #pragma unroll
        for (int j = 0; j < 4; j++) {
            int c = n0 + tx * 4 + j;
            float bias = cw.x * b2[0 * C_DIM + c] + cw.y * b2[1 * C_DIM + c]
                       + cw.z * b2[2 * C_DIM + c] + cw.w * b2[3 * C_DIM + c];
            out[(size_t)t * C_DIM + c] = acc[i][j] + bias;
        }
    }
}

// ---------------------------------------------------------------------------
extern "C" void kernel_launch(void* const* d_in, const int* in_sizes, int n_in,
                              void* d_out, int out_size)
{
    const float* x  = (const float*)d_in[0];   // [32,32,32,768]
    const float* rw = (const float*)d_in[1];   // [4,768]
    const float* rb = (const float*)d_in[2];   // [4]
    const float* w1 = (const float*)d_in[3];   // [4,192,768]
    const float* b1 = (const float*)d_in[4];   // [4,192]
    const float* w2 = (const float*)d_in[5];   // [4,768,192]
    const float* b2 = (const float*)d_in[6];   // [4,768]
    float* out = (float*)d_out;                // [32,32,32,768]

    router_kernel<<<T_TOK / 8, 256>>>(x, rw, rb);
    fc1_kernel<<<dim3(HD_DIM / BN, T_TOK / BM, E_NUM), 256>>>(x, w1, b1);
    fc2_kernel<<<dim3(C_DIM / BN, T_TOK / BM), 256>>>(w2, b2, out);
}

// round 3
// speedup vs baseline: 5.7874x; 5.7874x over previous
#include <cuda_runtime.h>
#include <math.h>
#include <stdint.h>

#define T_TOK 32768
#define C_DIM 768
#define E_NUM 4
#define HD_DIM 192
#define KB 32
#define NK (C_DIM / KB)          // 24
#define AS 36                    // padded smem row stride (floats)
#define STG_F (2 * 128 * AS)     // floats per stage (A tile + B tile)

__device__ float g_combine[T_TOK * E_NUM];            // 512 KB
__device__ float g_hmid[(size_t)T_TOK * C_DIM];       // 96 MB

// ---------------- helpers ----------------
__device__ __forceinline__ uint32_t smem_u32(const void* p) {
    uint32_t a;
    asm("{ .reg .u64 t; cvta.to.shared.u64 t, %1; cvt.u32.u64 %0, t; }" : "=r"(a) : "l"(p));
    return a;
}
#define CPA(s, g)  asm volatile("cp.async.cg.shared.global [%0], [%1], 16;" :: "r"(s), "l"(g))
#define CPC()      asm volatile("cp.async.commit_group;" ::: "memory")
#define CPW(n)     asm volatile("cp.async.wait_group %0;" :: "n"(n) : "memory")

__device__ __forceinline__ uint32_t cvt_tf32(float f) {
    uint32_t u;
    asm("cvt.rna.tf32.f32 %0, %1;" : "=r"(u) : "f"(f));
    return u;
}
#define MMA8(c, a, b)                                                                   \
    asm volatile("mma.sync.aligned.m16n8k8.row.col.f32.tf32.tf32.f32 "                  \
                 "{%0,%1,%2,%3},{%4,%5,%6,%7},{%8,%9},{%0,%1,%2,%3};"                   \
                 : "+f"((c)[0]), "+f"((c)[1]), "+f"((c)[2]), "+f"((c)[3])               \
                 : "r"((a)[0]), "r"((a)[1]), "r"((a)[2]), "r"((a)[3]),                  \
                   "r"((b)[0]), "r"((b)[1]))

// 128-row x 32-float tile loader: 1024 16B chunks over 256 threads
__device__ __forceinline__ void ld_tile(float* s, const float* __restrict__ g,
                                        int ldg, int tid) {
    #pragma unroll
    for (int c = tid; c < 1024; c += 256) {
        int row = c >> 3, k4 = c & 7;
        CPA(smem_u32(s + row * AS + k4 * 4), g + (size_t)row * ldg + k4 * 4);
    }
}

// ---------------------------------------------------------------------------
// Router (unchanged; ~42us)
// ---------------------------------------------------------------------------
__global__ __launch_bounds__(256) void router_kernel(
    const float* __restrict__ x, const float* __restrict__ rw, const float* __restrict__ rb)
{
    int warp = threadIdx.x >> 5, lane = threadIdx.x & 31;
    int t = blockIdx.x * 8 + warp;
    const float* xr = x + (size_t)t * C_DIM;
    float a0 = 0.f, a1 = 0.f, a2 = 0.f, a3 = 0.f;
    for (int c = lane * 4; c < C_DIM; c += 128) {
        float4 xv = *(const float4*)(xr + c);
        float4 w0 = *(const float4*)(rw + 0 * C_DIM + c);
        float4 w1 = *(const float4*)(rw + 1 * C_DIM + c);
        float4 w2 = *(const float4*)(rw + 2 * C_DIM + c);
        float4 w3 = *(const float4*)(rw + 3 * C_DIM + c);
        a0 += xv.x*w0.x + xv.y*w0.y + xv.z*w0.z + xv.w*w0.w;
        a1 += xv.x*w1.x + xv.y*w1.y + xv.z*w1.z + xv.w*w1.w;
        a2 += xv.x*w2.x + xv.y*w2.y + xv.z*w2.z + xv.w*w2.w;
        a3 += xv.x*w3.x + xv.y*w3.y + xv.z*w3.z + xv.w*w3.w;
    }
    #pragma unroll
    for (int o = 16; o > 0; o >>= 1) {
        a0 += __shfl_xor_sync(0xffffffffu, a0, o);
        a1 += __shfl_xor_sync(0xffffffffu, a1, o);
        a2 += __shfl_xor_sync(0xffffffffu, a2, o);
        a3 += __shfl_xor_sync(0xffffffffu, a3, o);
    }
    if (lane == 0) {
        float l[4] = { a0 + rb[0], a1 + rb[1], a2 + rb[2], a3 + rb[3] };
        float mx = fmaxf(fmaxf(l[0], l[1]), fmaxf(l[2], l[3]));
        float p[4]; float Z = 0.f;
        #pragma unroll
        for (int e = 0; e < 4; e++) { p[e] = expf(l[e] - mx); Z += p[e]; }
        #pragma unroll
        for (int e = 0; e < 4; e++) p[e] /= Z;
        int i0 = 0;
        #pragma unroll
        for (int e = 1; e < 4; e++) if (p[e] > p[i0]) i0 = e;
        int i1 = (i0 == 0) ? 1 : 0;
        #pragma unroll
        for (int e = 0; e < 4; e++) if (e != i0 && p[e] > p[i1]) i1 = e;
        float s = p[i0] + p[i1] + 1e-8f;
        float ov[4] = {0.f, 0.f, 0.f, 0.f};
        ov[i0] = p[i0] / s; ov[i1] = p[i1] / s;
        ((float4*)g_combine)[t] = make_float4(ov[0], ov[1], ov[2], ov[3]);
    }
}

// ---------------------------------------------------------------------------
// tf32 mma.sync GEMM, 128x128 tile, BK=32, depth-2 cp.async pipeline.
//  MODE 1: fc1 flat  A=x[T,768], B=w1 flat [768,768]  -> gelu*combine -> g_hmid
//  MODE 2: fc2       A=g_hmid,   B=w2 [E,C,HD] (per-k-tile base)     -> out
// ---------------------------------------------------------------------------
template <int MODE>
__global__ __launch_bounds__(256, 1)
void moe_mma(const float* __restrict__ A_in, const float* __restrict__ Bw,
             const float* __restrict__ bias, float* __restrict__ outp)
{
    extern __shared__ float sm[];
    const int tid = threadIdx.x, lane = tid & 31, w = tid >> 5;
    const int wm = w & 1, wn = w >> 1;          // warp grid 2 (M) x 4 (N)
    const int m0 = blockIdx.y * 128, n0 = blockIdx.x * 128;
    const int lq = lane >> 2, lr = lane & 3;

    const float* Ab = (MODE == 1 ? A_in : (const float*)g_hmid) + (size_t)m0 * C_DIM;
    const int ldB = (MODE == 1) ? C_DIM : HD_DIM;

    auto Bbase = [&](int i) -> const float* {
        const int k0 = i * KB;
        if (MODE == 1) return Bw + (size_t)n0 * C_DIM + k0;
        const int e = k0 / HD_DIM, h0 = k0 % HD_DIM;
        return Bw + (size_t)e * C_DIM * HD_DIM + (size_t)n0 * HD_DIM + h0;
    };

    float acc[4][4][4] = {};   // [mi][nj][reg]

    // prologue: iters 0,1 -> stages 0,1
    #pragma unroll
    for (int p = 0; p < 2; p++) {
        ld_tile(sm + p * STG_F, Ab + p * KB, C_DIM, tid);
        ld_tile(sm + p * STG_F + 128 * AS, Bbase(p), ldB, tid);
        CPC();
    }

    for (int i = 0; i < NK; i++) {
        if (i < NK - 1) { CPW(1); } else { CPW(0); }
        __syncthreads();
        if (i + 2 < NK) {
            const int s2 = (i + 2) % 3;
            ld_tile(sm + s2 * STG_F, Ab + (i + 2) * KB, C_DIM, tid);
            ld_tile(sm + s2 * STG_F + 128 * AS, Bbase(i + 2), ldB, tid);
            CPC();
        }
        const float* sA = sm + (i % 3) * STG_F;
        const float* sB = sA + 128 * AS;

        #pragma unroll
        for (int kk = 0; kk < 4; kk++) {
            const int kb = kk * 8 + lr;
            uint32_t a[4][4], b[4][2];
            #pragma unroll
            for (int mi = 0; mi < 4; mi++) {
                const int r = wm * 64 + mi * 16 + lq;
                a[mi][0] = cvt_tf32(sA[r * AS + kb]);
                a[mi][1] = cvt_tf32(sA[(r + 8) * AS + kb]);
                a[mi][2] = cvt_tf32(sA[r * AS + kb + 4]);
                a[mi][3] = cvt_tf32(sA[(r + 8) * AS + kb + 4]);
            }
            #pragma unroll
            for (int nj = 0; nj < 4; nj++) {
                const int r = wn * 32 + nj * 8 + lq;
                b[nj][0] = cvt_tf32(sB[r * AS + kb]);
                b[nj][1] = cvt_tf32(sB[r * AS + kb + 4]);
            }
            #pragma unroll
            for (int mi = 0; mi < 4; mi++)
                #pragma unroll
                for (int nj = 0; nj < 4; nj++)
                    MMA8(acc[mi][nj], a[mi], b[nj]);
        }
    }

    // ---------------- epilogue ----------------
    #pragma unroll
    for (int mi = 0; mi < 4; mi++) {
        const int t0 = m0 + wm * 64 + mi * 16 + lq;
        #pragma unroll
        for (int half = 0; half < 2; half++) {
            const int t = t0 + half * 8;
            if (MODE == 1) {
                const float4 cw4 = ((const float4*)g_combine)[t];
                const float* cwp = (const float*)&cw4;
                float* orow = g_hmid + (size_t)t * C_DIM;
                #pragma unroll
                for (int nj = 0; nj < 4; nj++) {
                    const int n = n0 + wn * 32 + nj * 8 + lr * 2;
                    const int e = n / HD_DIM;
                    const float cw = cwp[e];
                    float2 v;
                    #pragma unroll
                    for (int u = 0; u < 2; u++) {
                        float d = acc[mi][nj][half * 2 + u] + __ldg(&bias[n + u]);
                        float g = 0.5f * d * (1.0f + erff(d * 0.70710678118654752f));
                        ((float*)&v)[u] = g * cw;
                    }
                    *(float2*)(orow + n) = v;
                }
            } else {
                const float4 cw = ((const float4*)g_combine)[t];
                float* orow = outp + (size_t)t * C_DIM;
                #pragma unroll
                for (int nj = 0; nj < 4; nj++) {
                    const int n = n0 + wn * 32 + nj * 8 + lr * 2;
                    float2 v;
                    #pragma unroll
                    for (int u = 0; u < 2; u++) {
                        const int c = n + u;
                        float b = cw.x * __ldg(&bias[0 * C_DIM + c])
                                + cw.y * __ldg(&bias[1 * C_DIM + c])
                                + cw.z * __ldg(&bias[2 * C_DIM + c])
                                + cw.w * __ldg(&bias[3 * C_DIM + c]);
                        ((float*)&v)[u] = acc[mi][nj][half * 2 + u] + b;
                    }
                    *(float2*)(orow + n) = v;
                }
            }
        }
    }
}

// ---------------------------------------------------------------------------
extern "C" void kernel_launch(void* const* d_in, const int* in_sizes, int n_in,
                              void* d_out, int out_size)
{
    const float* x  = (const float*)d_in[0];
    const float* rw = (const float*)d_in[1];
    const float* rb = (const float*)d_in[2];
    const float* w1 = (const float*)d_in[3];   // [4,192,768] -> flat [768,768]
    const float* b1 = (const float*)d_in[4];   // [4,192] -> flat [768]
    const float* w2 = (const float*)d_in[5];   // [4,768,192]
    const float* b2 = (const float*)d_in[6];   // [4,768]
    float* out = (float*)d_out;

    const int SMEM = 3 * STG_F * sizeof(float);   // 110592 B
    cudaFuncSetAttribute(moe_mma<1>, cudaFuncAttributeMaxDynamicSharedMemorySize, SMEM);
    cudaFuncSetAttribute(moe_mma<2>, cudaFuncAttributeMaxDynamicSharedMemorySize, SMEM);

    router_kernel<<<T_TOK / 8, 256>>>(x, rw, rb);
    moe_mma<1><<<dim3(C_DIM / 128, T_TOK / 128), 256, SMEM>>>(x, w1, b1, nullptr);
    moe_mma<2><<<dim3(C_DIM / 128, T_TOK / 128), 256, SMEM>>>(nullptr, w2, b2, out);
}

// round 4
// speedup vs baseline: 8.1552x; 1.4091x over previous
#include <cuda_runtime.h>
#include <math.h>
#include <stdint.h>

#define T_TOK 32768
#define C_DIM 768
#define E_NUM 4
#define HD_DIM 192
#define KB 32
#define AS 36                    // padded smem row stride (floats)
#define STG_F (2 * 128 * AS)     // floats per stage (A tile + B tile)

__device__ float g_combine[T_TOK * E_NUM];            // 512 KB
__device__ int   g_pair[T_TOK];
__device__ int   g_cnt[8];
__device__ int   g_bucket[6 * T_TOK];
__device__ float g_hmid[(size_t)T_TOK * 384];         // 48 MB (pair-packed, token-indexed)

__constant__ int c_pairs[6][2] = {{0,1},{0,2},{0,3},{1,2},{1,3},{2,3}};

// ---------------- helpers ----------------
__device__ __forceinline__ uint32_t smem_u32(const void* p) {
    uint32_t a;
    asm("{ .reg .u64 t; cvta.to.shared.u64 t, %1; cvt.u32.u64 %0, t; }" : "=r"(a) : "l"(p));
    return a;
}
#define CPA(s, g)  asm volatile("cp.async.cg.shared.global [%0], [%1], 16;" :: "r"(s), "l"(g))
#define CPC()      asm volatile("cp.async.commit_group;" ::: "memory")
#define CPW(n)     asm volatile("cp.async.wait_group %0;" :: "n"(n) : "memory")

__device__ __forceinline__ uint32_t cvt_tf32(float f) {
    uint32_t u;
    asm("cvt.rna.tf32.f32 %0, %1;" : "=r"(u) : "f"(f));
    return u;
}
#define MMA8(c, a, b)                                                                   \
    asm volatile("mma.sync.aligned.m16n8k8.row.col.f32.tf32.tf32.f32 "                  \
                 "{%0,%1,%2,%3},{%4,%5,%6,%7},{%8,%9},{%0,%1,%2,%3};"                   \
                 : "+f"((c)[0]), "+f"((c)[1]), "+f"((c)[2]), "+f"((c)[3])               \
                 : "r"((a)[0]), "r"((a)[1]), "r"((a)[2]), "r"((a)[3]),                  \
                   "r"((b)[0]), "r"((b)[1]))

// 128-row x 32-float tile loader with per-row source pointers
template <typename F>
__device__ __forceinline__ void ld_tile_f(float* s, F rowptr, int tid) {
    #pragma unroll
    for (int c = tid; c < 1024; c += 256) {
        int row = c >> 3, k4 = c & 7;
        CPA(smem_u32(s + row * AS + k4 * 4), rowptr(row) + k4 * 4);
    }
}

// ---------------------------------------------------------------------------
// Router: warp per token -> combine weights + pair id. Block 0 zeroes counters.
// ---------------------------------------------------------------------------
__global__ __launch_bounds__(256) void router_kernel(
    const float* __restrict__ x, const float* __restrict__ rw, const float* __restrict__ rb)
{
    if (blockIdx.x == 0 && threadIdx.x < 8) g_cnt[threadIdx.x] = 0;
    int warp = threadIdx.x >> 5, lane = threadIdx.x & 31;
    int t = blockIdx.x * 8 + warp;
    const float* xr = x + (size_t)t * C_DIM;
    float a0 = 0.f, a1 = 0.f, a2 = 0.f, a3 = 0.f;
    for (int c = lane * 4; c < C_DIM; c += 128) {
        float4 xv = *(const float4*)(xr + c);
        float4 w0 = *(const float4*)(rw + 0 * C_DIM + c);
        float4 w1 = *(const float4*)(rw + 1 * C_DIM + c);
        float4 w2 = *(const float4*)(rw + 2 * C_DIM + c);
        float4 w3 = *(const float4*)(rw + 3 * C_DIM + c);
        a0 += xv.x*w0.x + xv.y*w0.y + xv.z*w0.z + xv.w*w0.w;
        a1 += xv.x*w1.x + xv.y*w1.y + xv.z*w1.z + xv.w*w1.w;
        a2 += xv.x*w2.x + xv.y*w2.y + xv.z*w2.z + xv.w*w2.w;
        a3 += xv.x*w3.x + xv.y*w3.y + xv.z*w3.z + xv.w*w3.w;
    }
    #pragma unroll
    for (int o = 16; o > 0; o >>= 1) {
        a0 += __shfl_xor_sync(0xffffffffu, a0, o);
        a1 += __shfl_xor_sync(0xffffffffu, a1, o);
        a2 += __shfl_xor_sync(0xffffffffu, a2, o);
        a3 += __shfl_xor_sync(0xffffffffu, a3, o);
    }
    if (lane == 0) {
        float l[4] = { a0 + rb[0], a1 + rb[1], a2 + rb[2], a3 + rb[3] };
        float mx = fmaxf(fmaxf(l[0], l[1]), fmaxf(l[2], l[3]));
        float p[4]; float Z = 0.f;
        #pragma unroll
        for (int e = 0; e < 4; e++) { p[e] = expf(l[e] - mx); Z += p[e]; }
        #pragma unroll
        for (int e = 0; e < 4; e++) p[e] /= Z;
        int i0 = 0;
        #pragma unroll
        for (int e = 1; e < 4; e++) if (p[e] > p[i0]) i0 = e;
        int i1 = (i0 == 0) ? 1 : 0;
        #pragma unroll
        for (int e = 0; e < 4; e++) if (e != i0 && p[e] > p[i1]) i1 = e;
        float s = p[i0] + p[i1] + 1e-8f;
        float ov[4] = {0.f, 0.f, 0.f, 0.f};
        ov[i0] = p[i0] / s; ov[i1] = p[i1] / s;
        ((float4*)g_combine)[t] = make_float4(ov[0], ov[1], ov[2], ov[3]);
        int lo = min(i0, i1), hi = max(i0, i1);
        g_pair[t] = (lo == 0) ? hi - 1 : ((lo == 1) ? hi + 1 : 5);
    }
}

// ---------------------------------------------------------------------------
// Bucketize: warp-aggregated atomic append of token ids into 6 pair buckets.
// ---------------------------------------------------------------------------
__global__ __launch_bounds__(256) void bucketize_kernel()
{
    int t = blockIdx.x * 256 + threadIdx.x;
    int pid = g_pair[t];
    unsigned mask = __match_any_sync(0xffffffffu, pid);
    int leader = __ffs(mask) - 1;
    int rank = __popc(mask & ((1u << (threadIdx.x & 31)) - 1));
    int base = 0;
    if ((threadIdx.x & 31) == leader) base = atomicAdd(&g_cnt[pid], __popc(mask));
    base = __shfl_sync(0xffffffffu, base, leader);
    g_bucket[pid * T_TOK + base + rank] = t;
}

// ---------------------------------------------------------------------------
// Grouped tf32 mma.sync GEMM over pair buckets, 128x128 tile, BK=32.
//  MODE 1 (fc1): K=768, NTOT=384 (w1[e0];w1[e1]), gelu*combine -> g_hmid[tok,384]
//  MODE 2 (fc2): K=384, NTOT=768 (w2 k-stacked),  +weighted bias -> out[tok,768]
// ---------------------------------------------------------------------------
template <int MODE>
__global__ __launch_bounds__(256, 1)
void moe_mma(const float* __restrict__ x, const float* __restrict__ Bw,
             const float* __restrict__ bias, float* __restrict__ outp)
{
    constexpr int NKI = (MODE == 1) ? (C_DIM / KB) : (384 / KB);   // 24 / 12
    extern __shared__ float sm[];
    int* stok = (int*)(sm + 3 * STG_F);

    const int b = blockIdx.z;
    const int cnt = __ldg(&g_cnt[b]);
    const int m0 = blockIdx.y * 128;
    if (m0 >= cnt) return;
    const int n0 = blockIdx.x * 128;
    const int e0 = c_pairs[b][0], e1 = c_pairs[b][1];

    const int tid = threadIdx.x, lane = tid & 31, w = tid >> 5;
    const int wm = w & 1, wn = w >> 1;
    const int lq = lane >> 2, lr = lane & 3;

    if (tid < 128) {
        int p = m0 + tid;
        stok[tid] = g_bucket[b * T_TOK + (p < cnt ? p : m0)];
    }
    __syncthreads();

    auto Arow = [&](int i) {
        return [=](int row) -> const float* {
            if (MODE == 1) return x + (size_t)stok[row] * C_DIM + i * KB;
            else           return (const float*)g_hmid + (size_t)stok[row] * 384 + i * KB;
        };
    };
    auto Brow = [&](int i) {
        return [=](int row) -> const float* {
            if (MODE == 1) {
                int n = n0 + row;                              // 0..383
                int e = (n < HD_DIM) ? e0 : e1;
                int h = (n < HD_DIM) ? n : n - HD_DIM;
                return Bw + ((size_t)e * HD_DIM + h) * C_DIM + i * KB;
            } else {
                int k0 = i * KB;                               // 0..352
                int e = (k0 < HD_DIM) ? e0 : e1;
                int h = (k0 < HD_DIM) ? k0 : k0 - HD_DIM;
                int c = n0 + row;                              // 0..767
                return Bw + ((size_t)e * C_DIM + c) * HD_DIM + h;
            }
        };
    };

    float acc[4][4][4] = {};

    #pragma unroll
    for (int p = 0; p < 2; p++) {
        ld_tile_f(sm + p * STG_F, Arow(p), tid);
        ld_tile_f(sm + p * STG_F + 128 * AS, Brow(p), tid);
        CPC();
    }

    for (int i = 0; i < NKI; i++) {
        if (i < NKI - 1) { CPW(1); } else { CPW(0); }
        __syncthreads();
        if (i + 2 < NKI) {
            const int s2 = (i + 2) % 3;
            ld_tile_f(sm + s2 * STG_F, Arow(i + 2), tid);
            ld_tile_f(sm + s2 * STG_F + 128 * AS, Brow(i + 2), tid);
            CPC();
        }
        const float* sA = sm + (i % 3) * STG_F;
        const float* sB = sA + 128 * AS;

        #pragma unroll
        for (int kk = 0; kk < 4; kk++) {
            const int kb = kk * 8 + lr;
            uint32_t a[4][4], bb[4][2];
            #pragma unroll
            for (int mi = 0; mi < 4; mi++) {
                const int r = wm * 64 + mi * 16 + lq;
                a[mi][0] = cvt_tf32(sA[r * AS + kb]);
                a[mi][1] = cvt_tf32(sA[(r + 8) * AS + kb]);
                a[mi][2] = cvt_tf32(sA[r * AS + kb + 4]);
                a[mi][3] = cvt_tf32(sA[(r + 8) * AS + kb + 4]);
            }
            #pragma unroll
            for (int nj = 0; nj < 4; nj++) {
                const int r = wn * 32 + nj * 8 + lq;
                bb[nj][0] = cvt_tf32(sB[r * AS + kb]);
                bb[nj][1] = cvt_tf32(sB[r * AS + kb + 4]);
            }
            #pragma unroll
            for (int mi = 0; mi < 4; mi++)
                #pragma unroll
                for (int nj = 0; nj < 4; nj++)
                    MMA8(acc[mi][nj], a[mi], bb[nj]);
        }
    }

    // ---------------- epilogue ----------------
    #pragma unroll
    for (int mi = 0; mi < 4; mi++) {
        #pragma unroll
        for (int half = 0; half < 2; half++) {
            const int rloc = wm * 64 + mi * 16 + lq + half * 8;
            if (m0 + rloc >= cnt) continue;
            const int t = stok[rloc];
            if (MODE == 1) {
                float* orow = g_hmid + (size_t)t * 384;
                #pragma unroll
                for (int nj = 0; nj < 4; nj++) {
                    const int n = n0 + wn * 32 + nj * 8 + lr * 2;
                    const int e = (n < HD_DIM) ? e0 : e1;
                    const int h = (n < HD_DIM) ? n : n - HD_DIM;
                    const float cw = g_combine[t * 4 + e];
                    float2 v;
                    #pragma unroll
                    for (int u = 0; u < 2; u++) {
                        float d = acc[mi][nj][half * 2 + u] + __ldg(&bias[e * HD_DIM + h + u]);
                        float g = 0.5f * d * (1.0f + erff(d * 0.70710678118654752f));
                        ((float*)&v)[u] = g * cw;
                    }
                    *(float2*)(orow + n) = v;
                }
            } else {
                const float4 cw = ((const float4*)g_combine)[t];
                float* orow = outp + (size_t)t * C_DIM;
                #pragma unroll
                for (int nj = 0; nj < 4; nj++) {
                    const int n = n0 + wn * 32 + nj * 8 + lr * 2;
                    float2 v;
                    #pragma unroll
                    for (int u = 0; u < 2; u++) {
                        const int c = n + u;
                        float bv = cw.x * __ldg(&bias[0 * C_DIM + c])
                                 + cw.y * __ldg(&bias[1 * C_DIM + c])
                                 + cw.z * __ldg(&bias[2 * C_DIM + c])
                                 + cw.w * __ldg(&bias[3 * C_DIM + c]);
                        ((float*)&v)[u] = acc[mi][nj][half * 2 + u] + bv;
                    }
                    *(float2*)(orow + n) = v;
                }
            }
        }
    }
}

// ---------------------------------------------------------------------------
extern "C" void kernel_launch(void* const* d_in, const int* in_sizes, int n_in,
                              void* d_out, int out_size)
{
    const float* x  = (const float*)d_in[0];
    const float* rw = (const float*)d_in[1];
    const float* rb = (const float*)d_in[2];
    const float* w1 = (const float*)d_in[3];
    const float* b1 = (const float*)d_in[4];
    const float* w2 = (const float*)d_in[5];
    const float* b2 = (const float*)d_in[6];
    float* out = (float*)d_out;

    const int SMEM = 3 * STG_F * sizeof(float) + 128 * sizeof(int);   // 111104 B
    cudaFuncSetAttribute(moe_mma<1>, cudaFuncAttributeMaxDynamicSharedMemorySize, SMEM);
    cudaFuncSetAttribute(moe_mma<2>, cudaFuncAttributeMaxDynamicSharedMemorySize, SMEM);

    router_kernel<<<T_TOK / 8, 256>>>(x, rw, rb);
    bucketize_kernel<<<T_TOK / 256, 256>>>();
    moe_mma<1><<<dim3(3, T_TOK / 128, 6), 256, SMEM>>>(x, w1, b1, nullptr);
    moe_mma<2><<<dim3(6, T_TOK / 128, 6), 256, SMEM>>>(x, w2, b2, out);
}

// round 6
// speedup vs baseline: 8.3698x; 1.0263x over previous
#include <cuda_runtime.h>
#include <math.h>
#include <stdint.h>

#define T_TOK 32768
#define C_DIM 768
#define E_NUM 4
#define HD_DIM 192
#define KB 32
#define AS 36                    // padded smem row stride (floats)
#define STG_F (2 * 128 * AS)     // floats per stage (A tile + B tile)

__device__ float g_combine[T_TOK * E_NUM];            // 512 KB
__device__ int   g_pair[T_TOK];
__device__ int   g_cnt[8];
__device__ int   g_bucket[6 * T_TOK];
__device__ float g_xr[(size_t)T_TOK * C_DIM];         // 100 MB rna(x)
__device__ float g_hmid[(size_t)T_TOK * 384];         // 48 MB rna(gelu*cw), pair-packed
__device__ float g_w1r[E_NUM * HD_DIM * C_DIM];       // 2.4 MB rna(w1)
__device__ float g_w2r[E_NUM * C_DIM * HD_DIM];       // 2.4 MB rna(w2)

__constant__ int c_pairs[6][2] = {{0,1},{0,2},{0,3},{1,2},{1,3},{2,3}};

// ---------------- helpers ----------------
__device__ __forceinline__ uint32_t smem_u32(const void* p) {
    uint32_t a;
    asm("{ .reg .u64 t; cvta.to.shared.u64 t, %1; cvt.u32.u64 %0, t; }" : "=r"(a) : "l"(p));
    return a;
}
#define CPA(s, g)  asm volatile("cp.async.cg.shared.global [%0], [%1], 16;" :: "r"(s), "l"(g))
#define CPC()      asm volatile("cp.async.commit_group;" ::: "memory")
#define CPW(n)     asm volatile("cp.async.wait_group %0;" :: "n"(n) : "memory")

__device__ __forceinline__ float cvt_tf32f(float f) {
    uint32_t u;
    asm("cvt.rna.tf32.f32 %0, %1;" : "=r"(u) : "f"(f));
    return __uint_as_float(u);
}
#define MMA8(c, a, b)                                                                   \
    asm volatile("mma.sync.aligned.m16n8k8.row.col.f32.tf32.tf32.f32 "                  \
                 "{%0,%1,%2,%3},{%4,%5,%6,%7},{%8,%9},{%0,%1,%2,%3};"                   \
                 : "+f"((c)[0]), "+f"((c)[1]), "+f"((c)[2]), "+f"((c)[3])               \
                 : "r"((a)[0]), "r"((a)[1]), "r"((a)[2]), "r"((a)[3]),                  \
                   "r"((b)[0]), "r"((b)[1]))

template <typename F>
__device__ __forceinline__ void ld_tile_f(float* s, F rowptr, int tid) {
    #pragma unroll
    for (int c = tid; c < 1024; c += 256) {
        int row = c >> 3, k4 = c & 7;
        CPA(smem_u32(s + row * AS + k4 * 4), rowptr(row) + k4 * 4);
    }
}

// ---------------------------------------------------------------------------
// Pre-round weights to tf32 (rna) into device-global buffers.
// ---------------------------------------------------------------------------
__global__ __launch_bounds__(256) void round_w_kernel(const float* __restrict__ w1,
                                                      const float* __restrict__ w2)
{
    const int N1 = E_NUM * HD_DIM * C_DIM;
    int i = blockIdx.x * 256 + threadIdx.x;
    if (i < N1) {
        g_w1r[i] = cvt_tf32f(w1[i]);
        g_w2r[i] = cvt_tf32f(w2[i]);
    }
}

// ---------------------------------------------------------------------------
// Router: warp per token -> combine + pair id, and writes rna-rounded x row.
// ---------------------------------------------------------------------------
__global__ __launch_bounds__(256) void router_kernel(
    const float* __restrict__ x, const float* __restrict__ rw, const float* __restrict__ rb)
{
    if (blockIdx.x == 0 && threadIdx.x < 8) g_cnt[threadIdx.x] = 0;
    int warp = threadIdx.x >> 5, lane = threadIdx.x & 31;
    int t = blockIdx.x * 8 + warp;
    const float* xr = x + (size_t)t * C_DIM;
    float* xo = g_xr + (size_t)t * C_DIM;
    float a0 = 0.f, a1 = 0.f, a2 = 0.f, a3 = 0.f;
    for (int c = lane * 4; c < C_DIM; c += 128) {
        float4 xv = *(const float4*)(xr + c);
        float4 w0 = *(const float4*)(rw + 0 * C_DIM + c);
        float4 w1 = *(const float4*)(rw + 1 * C_DIM + c);
        float4 w2 = *(const float4*)(rw + 2 * C_DIM + c);
        float4 w3 = *(const float4*)(rw + 3 * C_DIM + c);
        a0 += xv.x*w0.x + xv.y*w0.y + xv.z*w0.z + xv.w*w0.w;
        a1 += xv.x*w1.x + xv.y*w1.y + xv.z*w1.z + xv.w*w1.w;
        a2 += xv.x*w2.x + xv.y*w2.y + xv.z*w2.z + xv.w*w2.w;
        a3 += xv.x*w3.x + xv.y*w3.y + xv.z*w3.z + xv.w*w3.w;
        float4 rv = make_float4(cvt_tf32f(xv.x), cvt_tf32f(xv.y),
                                cvt_tf32f(xv.z), cvt_tf32f(xv.w));
        *(float4*)(xo + c) = rv;
    }
    #pragma unroll
    for (int o = 16; o > 0; o >>= 1) {
        a0 += __shfl_xor_sync(0xffffffffu, a0, o);
        a1 += __shfl_xor_sync(0xffffffffu, a1, o);
        a2 += __shfl_xor_sync(0xffffffffu, a2, o);
        a3 += __shfl_xor_sync(0xffffffffu, a3, o);
    }
    if (lane == 0) {
        float l[4] = { a0 + rb[0], a1 + rb[1], a2 + rb[2], a3 + rb[3] };
        float mx = fmaxf(fmaxf(l[0], l[1]), fmaxf(l[2], l[3]));
        float p[4]; float Z = 0.f;
        #pragma unroll
        for (int e = 0; e < 4; e++) { p[e] = expf(l[e] - mx); Z += p[e]; }
        #pragma unroll
        for (int e = 0; e < 4; e++) p[e] /= Z;
        int i0 = 0;
        #pragma unroll
        for (int e = 1; e < 4; e++) if (p[e] > p[i0]) i0 = e;
        int i1 = (i0 == 0) ? 1 : 0;
        #pragma unroll
        for (int e = 0; e < 4; e++) if (e != i0 && p[e] > p[i1]) i1 = e;
        float s = p[i0] + p[i1] + 1e-8f;
        float ov[4] = {0.f, 0.f, 0.f, 0.f};
        ov[i0] = p[i0] / s; ov[i1] = p[i1] / s;
        ((float4*)g_combine)[t] = make_float4(ov[0], ov[1], ov[2], ov[3]);
        int lo = min(i0, i1), hi = max(i0, i1);
        g_pair[t] = (lo == 0) ? hi - 1 : ((lo == 1) ? hi + 1 : 5);
    }
}

// ---------------------------------------------------------------------------
// Bucketize: warp-aggregated atomic append of token ids into 6 pair buckets.
// ---------------------------------------------------------------------------
__global__ __launch_bounds__(256) void bucketize_kernel()
{
    int t = blockIdx.x * 256 + threadIdx.x;
    int pid = g_pair[t];
    unsigned mask = __match_any_sync(0xffffffffu, pid);
    int leader = __ffs(mask) - 1;
    int rank = __popc(mask & ((1u << (threadIdx.x & 31)) - 1));
    int base = 0;
    if ((threadIdx.x & 31) == leader) base = atomicAdd(&g_cnt[pid], __popc(mask));
    base = __shfl_sync(0xffffffffu, base, leader);
    g_bucket[pid * T_TOK + base + rank] = t;
}

// ---------------------------------------------------------------------------
// Grouped tf32 mma.sync GEMM over pair buckets; operands pre-rounded -> no cvt
// in the hot loop. Weight buffers referenced as device symbols INSIDE the
// kernel (host code cannot pass __device__ symbol addresses).
// ---------------------------------------------------------------------------
template <int MODE>
__global__ __launch_bounds__(256, 1)
void moe_mma(const float* __restrict__ bias, float* __restrict__ outp)
{
    constexpr int NKI = (MODE == 1) ? (C_DIM / KB) : (384 / KB);   // 24 / 12
    extern __shared__ float sm[];
    int* stok = (int*)(sm + 3 * STG_F);

    const float* __restrict__ Bw = (MODE == 1) ? g_w1r : g_w2r;

    const int b = blockIdx.z;
    const int cnt = __ldg(&g_cnt[b]);
    const int m0 = blockIdx.y * 128;
    if (m0 >= cnt) return;
    const int n0 = blockIdx.x * 128;
    const int e0 = c_pairs[b][0], e1 = c_pairs[b][1];

    const int tid = threadIdx.x, lane = tid & 31, w = tid >> 5;
    const int wm = w & 1, wn = w >> 1;
    const int lq = lane >> 2, lr = lane & 3;

    if (tid < 128) {
        int p = m0 + tid;
        stok[tid] = g_bucket[b * T_TOK + (p < cnt ? p : m0)];
    }
    __syncthreads();

    auto Arow = [&](int i) {
        return [=](int row) -> const float* {
            if (MODE == 1) return (const float*)g_xr + (size_t)stok[row] * C_DIM + i * KB;
            else           return (const float*)g_hmid + (size_t)stok[row] * 384 + i * KB;
        };
    };
    auto Brow = [&](int i) {
        return [=](int row) -> const float* {
            if (MODE == 1) {
                int n = n0 + row;
                int e = (n < HD_DIM) ? e0 : e1;
                int h = (n < HD_DIM) ? n : n - HD_DIM;
                return Bw + ((size_t)e * HD_DIM + h) * C_DIM + i * KB;
            } else {
                int k0 = i * KB;
                int e = (k0 < HD_DIM) ? e0 : e1;
                int h = (k0 < HD_DIM) ? k0 : k0 - HD_DIM;
                int c = n0 + row;
                return Bw + ((size_t)e * C_DIM + c) * HD_DIM + h;
            }
        };
    };

    float acc[4][4][4] = {};

    #pragma unroll
    for (int p = 0; p < 2; p++) {
        ld_tile_f(sm + p * STG_F, Arow(p), tid);
        ld_tile_f(sm + p * STG_F + 128 * AS, Brow(p), tid);
        CPC();
    }

    for (int i = 0; i < NKI; i++) {
        if (i < NKI - 1) { CPW(1); } else { CPW(0); }
        __syncthreads();
        if (i + 2 < NKI) {
            const int s2 = (i + 2) % 3;
            ld_tile_f(sm + s2 * STG_F, Arow(i + 2), tid);
            ld_tile_f(sm + s2 * STG_F + 128 * AS, Brow(i + 2), tid);
            CPC();
        }
        const uint32_t* sA = (const uint32_t*)(sm + (i % 3) * STG_F);
        const uint32_t* sB = sA + 128 * AS;

        #pragma unroll
        for (int kk = 0; kk < 4; kk++) {
            const int kb = kk * 8 + lr;
            uint32_t a[4][4], bb[4][2];
            #pragma unroll
            for (int mi = 0; mi < 4; mi++) {
                const int r = wm * 64 + mi * 16 + lq;
                a[mi][0] = sA[r * AS + kb];
                a[mi][1] = sA[(r + 8) * AS + kb];
                a[mi][2] = sA[r * AS + kb + 4];
                a[mi][3] = sA[(r + 8) * AS + kb + 4];
            }
            #pragma unroll
            for (int nj = 0; nj < 4; nj++) {
                const int r = wn * 32 + nj * 8 + lq;
                bb[nj][0] = sB[r * AS + kb];
                bb[nj][1] = sB[r * AS + kb + 4];
            }
            #pragma unroll
            for (int mi = 0; mi < 4; mi++)
                #pragma unroll
                for (int nj = 0; nj < 4; nj++)
                    MMA8(acc[mi][nj], a[mi], bb[nj]);
        }
    }

    // ---------------- epilogue ----------------
    #pragma unroll
    for (int mi = 0; mi < 4; mi++) {
        #pragma unroll
        for (int half = 0; half < 2; half++) {
            const int rloc = wm * 64 + mi * 16 + lq + half * 8;
            if (m0 + rloc >= cnt) continue;
            const int t = stok[rloc];
            if (MODE == 1) {
                float* orow = g_hmid + (size_t)t * 384;
                #pragma unroll
                for (int nj = 0; nj < 4; nj++) {
                    const int n = n0 + wn * 32 + nj * 8 + lr * 2;
                    const int e = (n < HD_DIM) ? e0 : e1;
                    const int h = (n < HD_DIM) ? n : n - HD_DIM;
                    const float cw = g_combine[t * 4 + e];
                    float2 v;
                    #pragma unroll
                    for (int u = 0; u < 2; u++) {
                        float d = acc[mi][nj][half * 2 + u] + __ldg(&bias[e * HD_DIM + h + u]);
                        float g = 0.5f * d * (1.0f + erff(d * 0.70710678118654752f));
                        ((float*)&v)[u] = cvt_tf32f(g * cw);
                    }
                    *(float2*)(orow + n) = v;
                }
            } else {
                const float4 cw = ((const float4*)g_combine)[t];
                float* orow = outp + (size_t)t * C_DIM;
                #pragma unroll
                for (int nj = 0; nj < 4; nj++) {
                    const int n = n0 + wn * 32 + nj * 8 + lr * 2;
                    float2 v;
                    #pragma unroll
                    for (int u = 0; u < 2; u++) {
                        const int c = n + u;
                        float bv = cw.x * __ldg(&bias[0 * C_DIM + c])
                                 + cw.y * __ldg(&bias[1 * C_DIM + c])
                                 + cw.z * __ldg(&bias[2 * C_DIM + c])
                                 + cw.w * __ldg(&bias[3 * C_DIM + c]);
                        ((float*)&v)[u] = acc[mi][nj][half * 2 + u] + bv;
                    }
                    *(float2*)(orow + n) = v;
                }
            }
        }
    }
}

// ---------------------------------------------------------------------------
extern "C" void kernel_launch(void* const* d_in, const int* in_sizes, int n_in,
                              void* d_out, int out_size)
{
    const float* x  = (const float*)d_in[0];
    const float* rw = (const float*)d_in[1];
    const float* rb = (const float*)d_in[2];
    const float* w1 = (const float*)d_in[3];
    const float* b1 = (const float*)d_in[4];
    const float* w2 = (const float*)d_in[5];
    const float* b2 = (const float*)d_in[6];
    float* out = (float*)d_out;

    const int SMEM = 3 * STG_F * sizeof(float) + 128 * sizeof(int);
    cudaFuncSetAttribute(moe_mma<1>, cudaFuncAttributeMaxDynamicSharedMemorySize, SMEM);
    cudaFuncSetAttribute(moe_mma<2>, cudaFuncAttributeMaxDynamicSharedMemorySize, SMEM);

    round_w_kernel<<<(E_NUM * HD_DIM * C_DIM + 255) / 256, 256>>>(w1, w2);
    router_kernel<<<T_TOK / 8, 256>>>(x, rw, rb);
    bucketize_kernel<<<T_TOK / 256, 256>>>();
    moe_mma<1><<<dim3(3, T_TOK / 128, 6), 256, SMEM>>>(b1, nullptr);
    moe_mma<2><<<dim3(6, T_TOK / 128, 6), 256, SMEM>>>(b2, out);
}

// round 7
// speedup vs baseline: 17.0859x; 2.0414x over previous
#include <cuda_runtime.h>
#include <cuda_fp16.h>
#include <math.h>
#include <stdint.h>

#define T_TOK 32768
#define C_DIM 768
#define E_NUM 4
#define HD_DIM 192
#define KB 32                           // 32 halfs per k-iter (64B rows)
#define STG_B 16384                     // bytes per stage: A 8KB + B 8KB
#define SMEM_TOT (3 * STG_B + 512)

__device__ float  g_combine[T_TOK * E_NUM];
__device__ int    g_pair[T_TOK];
__device__ int    g_cnt[8];
__device__ int    g_bucket[6 * T_TOK];
__device__ __half g_xh[(size_t)T_TOK * C_DIM];        // 50 MB fp16(x)
__device__ __half g_hmid[(size_t)T_TOK * 384];        // 25 MB fp16(gelu*cw), pair-packed
__device__ __half g_w1h[E_NUM * HD_DIM * C_DIM];      // 1.2 MB
__device__ __half g_w2h[E_NUM * C_DIM * HD_DIM];      // 1.2 MB

__constant__ int c_pairs[6][2] = {{0,1},{0,2},{0,3},{1,2},{1,3},{2,3}};

// ---------------- helpers ----------------
__device__ __forceinline__ uint32_t smem_u32(const void* p) {
    uint32_t a;
    asm("{ .reg .u64 t; cvta.to.shared.u64 t, %1; cvt.u32.u64 %0, t; }" : "=r"(a) : "l"(p));
    return a;
}
#define CPA(s, g)  asm volatile("cp.async.cg.shared.global [%0], [%1], 16;" :: "r"(s), "l"(g))
#define CPC()      asm volatile("cp.async.commit_group;" ::: "memory")
#define CPW(n)     asm volatile("cp.async.wait_group %0;" :: "n"(n) : "memory")

#define LDSM4(r0, r1, r2, r3, addr)                                                     \
    asm volatile("ldmatrix.sync.aligned.m8n8.x4.shared.b16 {%0,%1,%2,%3}, [%4];"        \
                 : "=r"(r0), "=r"(r1), "=r"(r2), "=r"(r3) : "r"(addr))

#define MMA16(c, a, b)                                                                  \
    asm volatile("mma.sync.aligned.m16n8k16.row.col.f32.f16.f16.f32 "                   \
                 "{%0,%1,%2,%3},{%4,%5,%6,%7},{%8,%9},{%0,%1,%2,%3};"                   \
                 : "+f"((c)[0]), "+f"((c)[1]), "+f"((c)[2]), "+f"((c)[3])               \
                 : "r"((a)[0]), "r"((a)[1]), "r"((a)[2]), "r"((a)[3]),                  \
                   "r"((b)[0]), "r"((b)[1]))

// 128-row x 32-half tile: 512 x 16B chunks, swizzled (chunk ^ (row>>1)&3)
template <typename F>
__device__ __forceinline__ void ld_tile_h(uint32_t sbase, F rowptr, int tid) {
    #pragma unroll
    for (int c = tid; c < 512; c += 256) {
        int row = c >> 2, ch = c & 3;
        uint32_t off = (uint32_t)(row * 64 + ((ch ^ ((row >> 1) & 3)) << 4));
        CPA(sbase + off, rowptr(row) + ch * 8);
    }
}

// ---------------------------------------------------------------------------
// Pre-convert weights to fp16.
// ---------------------------------------------------------------------------
__global__ __launch_bounds__(256) void round_w_kernel(const float* __restrict__ w1,
                                                      const float* __restrict__ w2)
{
    const int N1 = E_NUM * HD_DIM * C_DIM;
    int i = blockIdx.x * 256 + threadIdx.x;
    if (i < N1) {
        g_w1h[i] = __float2half_rn(w1[i]);
        g_w2h[i] = __float2half_rn(w2[i]);
    }
}

// ---------------------------------------------------------------------------
// Router: warp per token -> combine + pair id; writes fp16 x row.
// ---------------------------------------------------------------------------
__global__ __launch_bounds__(256) void router_kernel(
    const float* __restrict__ x, const float* __restrict__ rw, const float* __restrict__ rb)
{
    if (blockIdx.x == 0 && threadIdx.x < 8) g_cnt[threadIdx.x] = 0;
    int warp = threadIdx.x >> 5, lane = threadIdx.x & 31;
    int t = blockIdx.x * 8 + warp;
    const float* xr = x + (size_t)t * C_DIM;
    __half* xo = g_xh + (size_t)t * C_DIM;
    float a0 = 0.f, a1 = 0.f, a2 = 0.f, a3 = 0.f;
    for (int c = lane * 4; c < C_DIM; c += 128) {
        float4 xv = *(const float4*)(xr + c);
        float4 w0 = *(const float4*)(rw + 0 * C_DIM + c);
        float4 w1 = *(const float4*)(rw + 1 * C_DIM + c);
        float4 w2 = *(const float4*)(rw + 2 * C_DIM + c);
        float4 w3 = *(const float4*)(rw + 3 * C_DIM + c);
        a0 += xv.x*w0.x + xv.y*w0.y + xv.z*w0.z + xv.w*w0.w;
        a1 += xv.x*w1.x + xv.y*w1.y + xv.z*w1.z + xv.w*w1.w;
        a2 += xv.x*w2.x + xv.y*w2.y + xv.z*w2.z + xv.w*w2.w;
        a3 += xv.x*w3.x + xv.y*w3.y + xv.z*w3.z + xv.w*w3.w;
        __half2 h0 = __floats2half2_rn(xv.x, xv.y);
        __half2 h1 = __floats2half2_rn(xv.z, xv.w);
        *(uint2*)(xo + c) = make_uint2(*(uint32_t*)&h0, *(uint32_t*)&h1);
    }
    #pragma unroll
    for (int o = 16; o > 0; o >>= 1) {
        a0 += __shfl_xor_sync(0xffffffffu, a0, o);
        a1 += __shfl_xor_sync(0xffffffffu, a1, o);
        a2 += __shfl_xor_sync(0xffffffffu, a2, o);
        a3 += __shfl_xor_sync(0xffffffffu, a3, o);
    }
    if (lane == 0) {
        float l[4] = { a0 + rb[0], a1 + rb[1], a2 + rb[2], a3 + rb[3] };
        float mx = fmaxf(fmaxf(l[0], l[1]), fmaxf(l[2], l[3]));
        float p[4]; float Z = 0.f;
        #pragma unroll
        for (int e = 0; e < 4; e++) { p[e] = expf(l[e] - mx); Z += p[e]; }
        #pragma unroll
        for (int e = 0; e < 4; e++) p[e] /= Z;
        int i0 = 0;
        #pragma unroll
        for (int e = 1; e < 4; e++) if (p[e] > p[i0]) i0 = e;
        int i1 = (i0 == 0) ? 1 : 0;
        #pragma unroll
        for (int e = 0; e < 4; e++) if (e != i0 && p[e] > p[i1]) i1 = e;
        float s = p[i0] + p[i1] + 1e-8f;
        float ov[4] = {0.f, 0.f, 0.f, 0.f};
        ov[i0] = p[i0] / s; ov[i1] = p[i1] / s;
        ((float4*)g_combine)[t] = make_float4(ov[0], ov[1], ov[2], ov[3]);
        int lo = min(i0, i1), hi = max(i0, i1);
        g_pair[t] = (lo == 0) ? hi - 1 : ((lo == 1) ? hi + 1 : 5);
    }
}

// ---------------------------------------------------------------------------
// Bucketize.
// ---------------------------------------------------------------------------
__global__ __launch_bounds__(256) void bucketize_kernel()
{
    int t = blockIdx.x * 256 + threadIdx.x;
    int pid = g_pair[t];
    unsigned mask = __match_any_sync(0xffffffffu, pid);
    int leader = __ffs(mask) - 1;
    int rank = __popc(mask & ((1u << (threadIdx.x & 31)) - 1));
    int base = 0;
    if ((threadIdx.x & 31) == leader) base = atomicAdd(&g_cnt[pid], __popc(mask));
    base = __shfl_sync(0xffffffffu, base, leader);
    g_bucket[pid * T_TOK + base + rank] = t;
}

// ---------------------------------------------------------------------------
// Grouped fp16 mma GEMM over pair buckets. 128x128 tile, KB=32, ldmatrix.
//  MODE 1 (fc1): A=g_xh K=768, B=g_w1h [384 rows], gelu*cw -> g_hmid (fp16)
//  MODE 2 (fc2): A=g_hmid K=384, B=g_w2h [768 rows], +wbias -> out (fp32)
// ---------------------------------------------------------------------------
template <int MODE>
__global__ __launch_bounds__(256, 2)
void moe_mma(const float* __restrict__ bias, float* __restrict__ outp)
{
    constexpr int NKI = (MODE == 1) ? (C_DIM / KB) : (384 / KB);   // 24 / 12
    extern __shared__ __align__(128) char smc[];
    const uint32_t sb = smem_u32(smc);
    int* stok = (int*)(smc + 3 * STG_B);

    const int b = blockIdx.z;
    const int cnt = __ldg(&g_cnt[b]);
    const int m0 = blockIdx.y * 128;
    if (m0 >= cnt) return;
    const int n0 = blockIdx.x * 128;
    const int e0 = c_pairs[b][0], e1 = c_pairs[b][1];

    const int tid = threadIdx.x, lane = tid & 31, w = tid >> 5;
    const int wm = w & 1, wn = w >> 1;
    const int lq = lane >> 2, lr = lane & 3;

    if (tid < 128) {
        int p = m0 + tid;
        stok[tid] = g_bucket[b * T_TOK + (p < cnt ? p : m0)];
    }
    __syncthreads();

    auto Arow = [&](int i) {
        return [=](int row) -> const __half* {
            if (MODE == 1) return (const __half*)g_xh + (size_t)stok[row] * C_DIM + i * KB;
            else           return (const __half*)g_hmid + (size_t)stok[row] * 384 + i * KB;
        };
    };
    auto Brow = [&](int i) {
        return [=](int row) -> const __half* {
            if (MODE == 1) {
                int n = n0 + row;
                int e = (n < HD_DIM) ? e0 : e1;
                int h = (n < HD_DIM) ? n : n - HD_DIM;
                return (const __half*)g_w1h + ((size_t)e * HD_DIM + h) * C_DIM + i * KB;
            } else {
                int k0 = i * KB;
                int e = (k0 < HD_DIM) ? e0 : e1;
                int h = (k0 < HD_DIM) ? k0 : k0 - HD_DIM;
                int c = n0 + row;
                return (const __half*)g_w2h + ((size_t)e * C_DIM + c) * HD_DIM + h;
            }
        };
    };

    // ldmatrix per-lane address components
    const int ms = lane >> 3, rl = lane & 7;
    const int sw = (rl >> 1) & 3;
    const int a_ms2 = ms >> 1;                      // chunk bit for A
    const int b_ms1 = ms & 1;                       // chunk bit for B
    uint32_t a_rowoff[4], b_rowoff[2];
    #pragma unroll
    for (int mi = 0; mi < 4; mi++)
        a_rowoff[mi] = (uint32_t)((wm * 64 + mi * 16 + (ms & 1) * 8 + rl) * 64);
    #pragma unroll
    for (int p = 0; p < 2; p++)
        b_rowoff[p] = (uint32_t)((wn * 32 + p * 16 + (ms >> 1) * 8 + rl) * 64);

    float acc[4][4][4] = {};

    #pragma unroll
    for (int p = 0; p < 2; p++) {
        ld_tile_h(sb + p * STG_B, Arow(p), tid);
        ld_tile_h(sb + p * STG_B + 8192, Brow(p), tid);
        CPC();
    }

    for (int i = 0; i < NKI; i++) {
        if (i < NKI - 1) { CPW(1); } else { CPW(0); }
        __syncthreads();
        if (i + 2 < NKI) {
            const int s2 = (i + 2) % 3;
            ld_tile_h(sb + s2 * STG_B, Arow(i + 2), tid);
            ld_tile_h(sb + s2 * STG_B + 8192, Brow(i + 2), tid);
            CPC();
        }
        const uint32_t smA = sb + (i % 3) * STG_B;
        const uint32_t smB = smA + 8192;

        #pragma unroll
        for (int kk = 0; kk < 2; kk++) {
            uint32_t a[4][4], bb[4][2];
            const uint32_t koffA = (uint32_t)(((2 * kk + a_ms2) ^ sw) << 4);
            const uint32_t koffB = (uint32_t)(((2 * kk + b_ms1) ^ sw) << 4);
            #pragma unroll
            for (int mi = 0; mi < 4; mi++)
                LDSM4(a[mi][0], a[mi][1], a[mi][2], a[mi][3], smA + a_rowoff[mi] + koffA);
            #pragma unroll
            for (int p = 0; p < 2; p++)
                LDSM4(bb[2*p][0], bb[2*p][1], bb[2*p+1][0], bb[2*p+1][1],
                      smB + b_rowoff[p] + koffB);
            #pragma unroll
            for (int mi = 0; mi < 4; mi++)
                #pragma unroll
                for (int nj = 0; nj < 4; nj++)
                    MMA16(acc[mi][nj], a[mi], bb[nj]);
        }
        __syncthreads();
    }

    // ---------------- epilogue ----------------
    #pragma unroll
    for (int mi = 0; mi < 4; mi++) {
        #pragma unroll
        for (int half = 0; half < 2; half++) {
            const int rloc = wm * 64 + mi * 16 + lq + half * 8;
            if (m0 + rloc >= cnt) continue;
            const int t = stok[rloc];
            if (MODE == 1) {
                __half* orow = g_hmid + (size_t)t * 384;
                #pragma unroll
                for (int nj = 0; nj < 4; nj++) {
                    const int n = n0 + wn * 32 + nj * 8 + lr * 2;
                    const int e = (n < HD_DIM) ? e0 : e1;
                    const int h = (n < HD_DIM) ? n : n - HD_DIM;
                    const float cw = g_combine[t * 4 + e];
                    float vv[2];
                    #pragma unroll
                    for (int u = 0; u < 2; u++) {
                        float d = acc[mi][nj][half * 2 + u] + __ldg(&bias[e * HD_DIM + h + u]);
                        float g = 0.5f * d * (1.0f + erff(d * 0.70710678118654752f));
                        vv[u] = g * cw;
                    }
                    __half2 hv = __floats2half2_rn(vv[0], vv[1]);
                    *(__half2*)(orow + n) = hv;
                }
            } else {
                const float4 cw = ((const float4*)g_combine)[t];
                float* orow = outp + (size_t)t * C_DIM;
                #pragma unroll
                for (int nj = 0; nj < 4; nj++) {
                    const int n = n0 + wn * 32 + nj * 8 + lr * 2;
                    float2 v;
                    #pragma unroll
                    for (int u = 0; u < 2; u++) {
                        const int c = n + u;
                        float bv = cw.x * __ldg(&bias[0 * C_DIM + c])
                                 + cw.y * __ldg(&bias[1 * C_DIM + c])
                                 + cw.z * __ldg(&bias[2 * C_DIM + c])
                                 + cw.w * __ldg(&bias[3 * C_DIM + c]);
                        ((float*)&v)[u] = acc[mi][nj][half * 2 + u] + bv;
                    }
                    *(float2*)(orow + n) = v;
                }
            }
        }
    }
}

// ---------------------------------------------------------------------------
extern "C" void kernel_launch(void* const* d_in, const int* in_sizes, int n_in,
                              void* d_out, int out_size)
{
    const float* x  = (const float*)d_in[0];
    const float* rw = (const float*)d_in[1];
    const float* rb = (const float*)d_in[2];
    const float* w1 = (const float*)d_in[3];
    const float* b1 = (const float*)d_in[4];
    const float* w2 = (const float*)d_in[5];
    const float* b2 = (const float*)d_in[6];
    float* out = (float*)d_out;

    cudaFuncSetAttribute(moe_mma<1>, cudaFuncAttributeMaxDynamicSharedMemorySize, SMEM_TOT);
    cudaFuncSetAttribute(moe_mma<2>, cudaFuncAttributeMaxDynamicSharedMemorySize, SMEM_TOT);

    round_w_kernel<<<(E_NUM * HD_DIM * C_DIM + 255) / 256, 256>>>(w1, w2);
    router_kernel<<<T_TOK / 8, 256>>>(x, rw, rb);
    bucketize_kernel<<<T_TOK / 256, 256>>>();
    moe_mma<1><<<dim3(3, T_TOK / 128, 6), 256, SMEM_TOT>>>(b1, nullptr);
    moe_mma<2><<<dim3(6, T_TOK / 128, 6), 256, SMEM_TOT>>>(b2, out);
}

// round 8
// speedup vs baseline: 17.2969x; 1.0124x over previous
#include <cuda_runtime.h>
#include <cuda_fp16.h>
#include <math.h>
#include <stdint.h>

#define T_TOK 32768
#define C_DIM 768
#define E_NUM 4
#define HD_DIM 192
#define KB 64                           // 64 halfs per k-iter (128B rows)
#define STG_B 32768                     // bytes per stage: A 16KB + B 16KB
#define SMEM_TOT (3 * STG_B + 512)

__device__ float  g_combine[T_TOK * E_NUM];
__device__ int    g_pair[T_TOK];
__device__ int    g_cnt[8];
__device__ int    g_bucket[6 * T_TOK];
__device__ __half g_xh[(size_t)T_TOK * C_DIM];        // 50 MB fp16(x)
__device__ __half g_hmid[(size_t)T_TOK * 384];        // 25 MB fp16(gelu*cw), pair-packed
__device__ __half g_w1h[E_NUM * HD_DIM * C_DIM];      // 1.2 MB
__device__ __half g_w2h[E_NUM * C_DIM * HD_DIM];      // 1.2 MB

__constant__ int c_pairs[6][2] = {{0,1},{0,2},{0,3},{1,2},{1,3},{2,3}};

// ---------------- helpers ----------------
__device__ __forceinline__ uint32_t smem_u32(const void* p) {
    uint32_t a;
    asm("{ .reg .u64 t; cvta.to.shared.u64 t, %1; cvt.u32.u64 %0, t; }" : "=r"(a) : "l"(p));
    return a;
}
#define CPA(s, g)  asm volatile("cp.async.cg.shared.global [%0], [%1], 16;" :: "r"(s), "l"(g))
#define CPC()      asm volatile("cp.async.commit_group;" ::: "memory")
#define CPW(n)     asm volatile("cp.async.wait_group %0;" :: "n"(n) : "memory")

#define LDSM4(r0, r1, r2, r3, addr)                                                     \
    asm volatile("ldmatrix.sync.aligned.m8n8.x4.shared.b16 {%0,%1,%2,%3}, [%4];"        \
                 : "=r"(r0), "=r"(r1), "=r"(r2), "=r"(r3) : "r"(addr))

#define MMA16(c, a, b)                                                                  \
    asm volatile("mma.sync.aligned.m16n8k16.row.col.f32.f16.f16.f32 "                   \
                 "{%0,%1,%2,%3},{%4,%5,%6,%7},{%8,%9},{%0,%1,%2,%3};"                   \
                 : "+f"((c)[0]), "+f"((c)[1]), "+f"((c)[2]), "+f"((c)[3])               \
                 : "r"((a)[0]), "r"((a)[1]), "r"((a)[2]), "r"((a)[3]),                  \
                   "r"((b)[0]), "r"((b)[1]))

// 128-row x 64-half tile: 1024 x 16B chunks, swizzle: chunk ^= (row & 7)
template <typename F>
__device__ __forceinline__ void ld_tile_h(uint32_t sbase, F rowptr, int tid) {
    #pragma unroll
    for (int c = tid; c < 1024; c += 256) {
        int row = c >> 3, ch = c & 7;
        uint32_t off = (uint32_t)(row * 128 + ((ch ^ (row & 7)) << 4));
        CPA(sbase + off, rowptr(row) + ch * 8);
    }
}

// ---------------------------------------------------------------------------
__global__ __launch_bounds__(256) void round_w_kernel(const float* __restrict__ w1,
                                                      const float* __restrict__ w2)
{
    const int N1 = E_NUM * HD_DIM * C_DIM;
    int i = blockIdx.x * 256 + threadIdx.x;
    if (i < N1) {
        g_w1h[i] = __float2half_rn(w1[i]);
        g_w2h[i] = __float2half_rn(w2[i]);
    }
}

// ---------------------------------------------------------------------------
// Router: warp per token -> combine + pair id; writes fp16 x row.
// ---------------------------------------------------------------------------
__global__ __launch_bounds__(256) void router_kernel(
    const float* __restrict__ x, const float* __restrict__ rw, const float* __restrict__ rb)
{
    if (blockIdx.x == 0 && threadIdx.x < 8) g_cnt[threadIdx.x] = 0;
    int warp = threadIdx.x >> 5, lane = threadIdx.x & 31;
    int t = blockIdx.x * 8 + warp;
    const float* xr = x + (size_t)t * C_DIM;
    __half* xo = g_xh + (size_t)t * C_DIM;
    float a0 = 0.f, a1 = 0.f, a2 = 0.f, a3 = 0.f;
    for (int c = lane * 4; c < C_DIM; c += 128) {
        float4 xv = *(const float4*)(xr + c);
        float4 w0 = *(const float4*)(rw + 0 * C_DIM + c);
        float4 w1 = *(const float4*)(rw + 1 * C_DIM + c);
        float4 w2 = *(const float4*)(rw + 2 * C_DIM + c);
        float4 w3 = *(const float4*)(rw + 3 * C_DIM + c);
        a0 += xv.x*w0.x + xv.y*w0.y + xv.z*w0.z + xv.w*w0.w;
        a1 += xv.x*w1.x + xv.y*w1.y + xv.z*w1.z + xv.w*w1.w;
        a2 += xv.x*w2.x + xv.y*w2.y + xv.z*w2.z + xv.w*w2.w;
        a3 += xv.x*w3.x + xv.y*w3.y + xv.z*w3.z + xv.w*w3.w;
        __half2 h0 = __floats2half2_rn(xv.x, xv.y);
        __half2 h1 = __floats2half2_rn(xv.z, xv.w);
        *(uint2*)(xo + c) = make_uint2(*(uint32_t*)&h0, *(uint32_t*)&h1);
    }
    #pragma unroll
    for (int o = 16; o > 0; o >>= 1) {
        a0 += __shfl_xor_sync(0xffffffffu, a0, o);
        a1 += __shfl_xor_sync(0xffffffffu, a1, o);
        a2 += __shfl_xor_sync(0xffffffffu, a2, o);
        a3 += __shfl_xor_sync(0xffffffffu, a3, o);
    }
    if (lane == 0) {
        float l[4] = { a0 + rb[0], a1 + rb[1], a2 + rb[2], a3 + rb[3] };
        float mx = fmaxf(fmaxf(l[0], l[1]), fmaxf(l[2], l[3]));
        float p[4]; float Z = 0.f;
        #pragma unroll
        for (int e = 0; e < 4; e++) { p[e] = expf(l[e] - mx); Z += p[e]; }
        #pragma unroll
        for (int e = 0; e < 4; e++) p[e] /= Z;
        int i0 = 0;
        #pragma unroll
        for (int e = 1; e < 4; e++) if (p[e] > p[i0]) i0 = e;
        int i1 = (i0 == 0) ? 1 : 0;
        #pragma unroll
        for (int e = 0; e < 4; e++) if (e != i0 && p[e] > p[i1]) i1 = e;
        float s = p[i0] + p[i1] + 1e-8f;
        float ov[4] = {0.f, 0.f, 0.f, 0.f};
        ov[i0] = p[i0] / s; ov[i1] = p[i1] / s;
        ((float4*)g_combine)[t] = make_float4(ov[0], ov[1], ov[2], ov[3]);
        int lo = min(i0, i1), hi = max(i0, i1);
        g_pair[t] = (lo == 0) ? hi - 1 : ((lo == 1) ? hi + 1 : 5);
    }
}

// ---------------------------------------------------------------------------
__global__ __launch_bounds__(256) void bucketize_kernel()
{
    int t = blockIdx.x * 256 + threadIdx.x;
    int pid = g_pair[t];
    unsigned mask = __match_any_sync(0xffffffffu, pid);
    int leader = __ffs(mask) - 1;
    int rank = __popc(mask & ((1u << (threadIdx.x & 31)) - 1));
    int base = 0;
    if ((threadIdx.x & 31) == leader) base = atomicAdd(&g_cnt[pid], __popc(mask));
    base = __shfl_sync(0xffffffffu, base, leader);
    g_bucket[pid * T_TOK + base + rank] = t;
}

// ---------------------------------------------------------------------------
// Grouped fp16 mma GEMM over pair buckets. 128x128 tile, KB=64, ldmatrix.
// ---------------------------------------------------------------------------
template <int MODE>
__global__ __launch_bounds__(256, 2)
void moe_mma(const float* __restrict__ bias, float* __restrict__ outp)
{
    constexpr int NKI = (MODE == 1) ? (C_DIM / KB) : (384 / KB);   // 12 / 6
    extern __shared__ __align__(128) char smc[];
    const uint32_t sb = smem_u32(smc);
    int* stok = (int*)(smc + 3 * STG_B);

    const int b = blockIdx.z;
    const int cnt = __ldg(&g_cnt[b]);
    const int m0 = blockIdx.y * 128;
    if (m0 >= cnt) return;
    const int n0 = blockIdx.x * 128;
    const int e0 = c_pairs[b][0], e1 = c_pairs[b][1];

    const int tid = threadIdx.x, lane = tid & 31, w = tid >> 5;
    const int wm = w & 1, wn = w >> 1;
    const int lq = lane >> 2, lr = lane & 3;

    if (tid < 128) {
        int p = m0 + tid;
        stok[tid] = g_bucket[b * T_TOK + (p < cnt ? p : m0)];
    }
    __syncthreads();

    auto Arow = [&](int i) {
        return [=](int row) -> const __half* {
            if (MODE == 1) return (const __half*)g_xh + (size_t)stok[row] * C_DIM + i * KB;
            else           return (const __half*)g_hmid + (size_t)stok[row] * 384 + i * KB;
        };
    };
    auto Brow = [&](int i) {
        return [=](int row) -> const __half* {
            if (MODE == 1) {
                int n = n0 + row;
                int e = (n < HD_DIM) ? e0 : e1;
                int h = (n < HD_DIM) ? n : n - HD_DIM;
                return (const __half*)g_w1h + ((size_t)e * HD_DIM + h) * C_DIM + i * KB;
            } else {
                int k0 = i * KB;
                int e = (k0 < HD_DIM) ? e0 : e1;
                int h = (k0 < HD_DIM) ? k0 : k0 - HD_DIM;
                int c = n0 + row;
                return (const __half*)g_w2h + ((size_t)e * C_DIM + c) * HD_DIM + h;
            }
        };
    };

    // ldmatrix per-lane address components (rows of 128B, swizzle chunk^=(row&7))
    const int ms = lane >> 3, rl = lane & 7;
    const int a_ms2 = ms >> 1;                      // k-chunk bit for A
    const int b_ms1 = ms & 1;                       // k-chunk bit for B
    uint32_t a_rowoff[4], b_rowoff[2];
    #pragma unroll
    for (int mi = 0; mi < 4; mi++)
        a_rowoff[mi] = (uint32_t)((wm * 64 + mi * 16 + (ms & 1) * 8 + rl) * 128);
    #pragma unroll
    for (int p = 0; p < 2; p++)
        b_rowoff[p] = (uint32_t)((wn * 32 + p * 16 + (ms >> 1) * 8 + rl) * 128);

    float acc[4][4][4] = {};

    #pragma unroll
    for (int p = 0; p < 2; p++) {
        ld_tile_h(sb + p * STG_B, Arow(p), tid);
        ld_tile_h(sb + p * STG_B + 16384, Brow(p), tid);
        CPC();
    }

    for (int i = 0; i < NKI; i++) {
        if (i < NKI - 1) { CPW(1); } else { CPW(0); }
        __syncthreads();
        if (i + 2 < NKI) {
            const int s2 = (i + 2) % 3;
            ld_tile_h(sb + s2 * STG_B, Arow(i + 2), tid);
            ld_tile_h(sb + s2 * STG_B + 16384, Brow(i + 2), tid);
            CPC();
        }
        const uint32_t smA = sb + (i % 3) * STG_B;
        const uint32_t smB = smA + 16384;

        #pragma unroll
        for (int kk = 0; kk < 4; kk++) {
            uint32_t a[4][4], bb[4][2];
            const uint32_t koffA = (uint32_t)(((2 * kk + a_ms2) ^ rl) << 4);
            const uint32_t koffB = (uint32_t)(((2 * kk + b_ms1) ^ rl) << 4);
            #pragma unroll
            for (int mi = 0; mi < 4; mi++)
                LDSM4(a[mi][0], a[mi][1], a[mi][2], a[mi][3], smA + a_rowoff[mi] + koffA);
            #pragma unroll
            for (int p = 0; p < 2; p++)
                LDSM4(bb[2*p][0], bb[2*p][1], bb[2*p+1][0], bb[2*p+1][1],
                      smB + b_rowoff[p] + koffB);
            #pragma unroll
            for (int mi = 0; mi < 4; mi++)
                #pragma unroll
                for (int nj = 0; nj < 4; nj++)
                    MMA16(acc[mi][nj], a[mi], bb[nj]);
        }
        __syncthreads();
    }

    // ---------------- epilogue ----------------
    #pragma unroll
    for (int mi = 0; mi < 4; mi++) {
        #pragma unroll
        for (int half = 0; half < 2; half++) {
            const int rloc = wm * 64 + mi * 16 + lq + half * 8;
            if (m0 + rloc >= cnt) continue;
            const int t = stok[rloc];
            if (MODE == 1) {
                __half* orow = g_hmid + (size_t)t * 384;
                #pragma unroll
                for (int nj = 0; nj < 4; nj++) {
                    const int n = n0 + wn * 32 + nj * 8 + lr * 2;
                    const int e = (n < HD_DIM) ? e0 : e1;
                    const int h = (n < HD_DIM) ? n : n - HD_DIM;
                    const float cw = g_combine[t * 4 + e];
                    float vv[2];
                    #pragma unroll
                    for (int u = 0; u < 2; u++) {
                        float d = acc[mi][nj][half * 2 + u] + __ldg(&bias[e * HD_DIM + h + u]);
                        float g = 0.5f * d * (1.0f + erff(d * 0.70710678118654752f));
                        vv[u] = g * cw;
                    }
                    __half2 hv = __floats2half2_rn(vv[0], vv[1]);
                    *(__half2*)(orow + n) = hv;
                }
            } else {
                const float4 cw = ((const float4*)g_combine)[t];
                float* orow = outp + (size_t)t * C_DIM;
                #pragma unroll
                for (int nj = 0; nj < 4; nj++) {
                    const int n = n0 + wn * 32 + nj * 8 + lr * 2;
                    float2 v;
                    #pragma unroll
                    for (int u = 0; u < 2; u++) {
                        const int c = n + u;
                        float bv = cw.x * __ldg(&bias[0 * C_DIM + c])
                                 + cw.y * __ldg(&bias[1 * C_DIM + c])
                                 + cw.z * __ldg(&bias[2 * C_DIM + c])
                                 + cw.w * __ldg(&bias[3 * C_DIM + c]);
                        ((float*)&v)[u] = acc[mi][nj][half * 2 + u] + bv;
                    }
                    *(float2*)(orow + n) = v;
                }
            }
        }
    }
}

// ---------------------------------------------------------------------------
extern "C" void kernel_launch(void* const* d_in, const int* in_sizes, int n_in,
                              void* d_out, int out_size)
{
    const float* x  = (const float*)d_in[0];
    const float* rw = (const float*)d_in[1];
    const float* rb = (const float*)d_in[2];
    const float* w1 = (const float*)d_in[3];
    const float* b1 = (const float*)d_in[4];
    const float* w2 = (const float*)d_in[5];
    const float* b2 = (const float*)d_in[6];
    float* out = (float*)d_out;

    cudaFuncSetAttribute(moe_mma<1>, cudaFuncAttributeMaxDynamicSharedMemorySize, SMEM_TOT);
    cudaFuncSetAttribute(moe_mma<2>, cudaFuncAttributeMaxDynamicSharedMemorySize, SMEM_TOT);

    round_w_kernel<<<(E_NUM * HD_DIM * C_DIM + 255) / 256, 256>>>(w1, w2);
    router_kernel<<<T_TOK / 8, 256>>>(x, rw, rb);
    bucketize_kernel<<<T_TOK / 256, 256>>>();
    moe_mma<1><<<dim3(3, T_TOK / 128, 6), 256, SMEM_TOT>>>(b1, nullptr);
    moe_mma<2><<<dim3(6, T_TOK / 128, 6), 256, SMEM_TOT>>>(b2, out);
}